// round 14
// baseline (speedup 1.0000x reference)
#include <cuda_runtime.h>
#include <math.h>
#include <stdint.h>

#define BB    8
#define CC    256
#define NROW  32768
#define INTER 1024
#define KCB   1024

typedef unsigned long long ull;

__device__ float g_A0[NROW * CC];
__device__ float g_A1[NROW * CC];
__device__ float g_LN[NROW * CC];
__device__ float g_C [NROW * INTER];
__device__ float g_grn[BB * INTER];
__device__ float g_scl[BB * INTER];
__device__ float g_r [NROW];
__device__ float g_cn[KCB];
__device__ ull   g_best[NROW];
__device__ float g_cwT[49 * CC];

__device__ __forceinline__ void fma2(float2& d, ull a2, const float2& b) {
    ull& dd = reinterpret_cast<ull&>(d);
    asm("fma.rn.f32x2 %0, %1, %2, %0;" : "+l"(dd)
        : "l"(a2), "l"(reinterpret_cast<const ull&>(b)));
}
__device__ __forceinline__ float warp_red(float v) {
    #pragma unroll
    for (int off = 16; off > 0; off >>= 1)
        v = __fadd_rn(v, __shfl_down_sync(0xffffffffu, v, off));
    return v;
}
__device__ __forceinline__ float combine8(const float* si) {
    float t0 = __fadd_rn(si[0], si[4]);
    float t1 = __fadd_rn(si[1], si[5]);
    float t2 = __fadd_rn(si[2], si[6]);
    float t3 = __fadd_rn(si[3], si[7]);
    return __fadd_rn(__fadd_rn(t0, t2), __fadd_rn(t1, t3));
}

__global__ void k_transpose(const float* __restrict__ in, float* __restrict__ out,
                            int R, int S) {
    __shared__ float tile[32][33];
    int b = blockIdx.z;
    int base = b * R * S;
    int s0 = blockIdx.x * 32, r0 = blockIdx.y * 32;
    int sx = s0 + threadIdx.x;
    for (int i = threadIdx.y; i < 32; i += 8)
        tile[i][threadIdx.x] = in[base + (r0 + i) * S + sx];
    __syncthreads();
    int rx = r0 + threadIdx.x;
    for (int i = threadIdx.y; i < 32; i += 8)
        out[base + (s0 + i) * R + rx] = tile[threadIdx.x][i];
}

__global__ void k_wtrans(const float* __restrict__ cw, float* __restrict__ cwT) {
    cwT[blockIdx.x * CC + threadIdx.x] = cw[threadIdx.x * 49 + blockIdx.x];
}

// ---------- depthwise conv 7x7 + bias + LayerNorm: 4x8-pixel 2D tile ---------
__global__ __launch_bounds__(256)
void k_conv_ln(const float* __restrict__ in, float* __restrict__ out,
               const float* __restrict__ cwT, const float* __restrict__ cb,
               const float* __restrict__ lng, const float* __restrict__ lnb) {
    __shared__ float spart[2][32][8];
    int g = threadIdx.x >> 5, l = threadIdx.x & 31, c = g * 32 + l;
    int idx = blockIdx.x;
    int b  = idx >> 7;
    int tile = idx & 127;
    int h0 = (tile >> 3) * 4;
    int w0 = (tile & 7) * 8;
    const float* base = in + ((long)b << 12) * CC;

    bool validw[14];
    #pragma unroll
    for (int j = 0; j < 14; j++) validw[j] = ((unsigned)(w0 + j - 3) < 64u);

    float acc[32];
    #pragma unroll
    for (int p = 0; p < 32; p++) acc[p] = 0.0f;

    #pragma unroll
    for (int ih = 0; ih < 10; ih++) {
        int hh = h0 + ih - 3;
        if ((unsigned)hh >= 64u) continue;
        const float* xrow = base + ((size_t)(hh << 6)) * CC + c;
        float xv[14];
        #pragma unroll
        for (int j = 0; j < 14; j++)
            xv[j] = validw[j] ? xrow[(w0 + j - 3) * CC] : 0.0f;
        #pragma unroll
        for (int kh = 0; kh < 7; kh++) {
            int ph = ih - kh;
            if (ph < 0 || ph > 3) continue;
            float wv[7];
            #pragma unroll
            for (int kw = 0; kw < 7; kw++)
                wv[kw] = cwT[(kh * 7 + kw) * CC + c];
            #pragma unroll
            for (int pw = 0; pw < 8; pw++)
                #pragma unroll
                for (int kw = 0; kw < 7; kw++)
                    if (validw[pw + kw])
                        acc[ph * 8 + pw] = __fmaf_rn(wv[kw], xv[pw + kw], acc[ph * 8 + pw]);
        }
    }

    float biasv = cb[c];
    #pragma unroll
    for (int p = 0; p < 32; p++) acc[p] = __fadd_rn(acc[p], biasv);

    #pragma unroll
    for (int p = 0; p < 32; p++) {
        float s = warp_red(acc[p]);
        if (l == 0) spart[0][p][g] = s;
    }
    __syncthreads();
    #pragma unroll
    for (int p = 0; p < 32; p++) {
        float mu = __fmul_rn(combine8(&spart[0][p][0]), 0.00390625f);
        acc[p] = __fsub_rn(acc[p], mu);
    }
    #pragma unroll
    for (int p = 0; p < 32; p++) {
        float s = warp_red(__fmul_rn(acc[p], acc[p]));
        if (l == 0) spart[1][p][g] = s;
    }
    __syncthreads();

    float gv = lng[c], bv = lnb[c];
    #pragma unroll
    for (int p = 0; p < 32; p++) {
        float var = __fmul_rn(combine8(&spart[1][p][0]), 0.00390625f);
        float rs = rsqrtf(__fadd_rn(var, 1e-5f));
        int gp = (b << 12) + ((h0 + (p >> 3)) << 6) + w0 + (p & 7);
        out[(size_t)gp * CC + c] =
            __fadd_rn(__fmul_rn(__fmul_rn(acc[p], rs), gv), bv);
    }
}

// ============================================================================
// GEMM core: 128x128 CTA tile, 256 threads, 8x8/thread, BK=16, double-buffered.
// A stored DUPLICATED in smem ({a,a} pairs); fragments read BY VALUE as
// ulonglong2 (LDS.128 -> two ready FFMA2 a-operands; no broadcast MOVs, no
// address-of-locals). Chains k-ascending per output -> bit-exact.
// ============================================================================
#define BM 128
#define BN 128
#define BK 16
#define ALDA (2 * BM + 4)
#define BPAD 4

#define MMA_STEP_DUP(acc, qa0, qa1, qa2, qa3, b0, b1)                         \
    {                                                                         \
        float2 p00 = make_float2(b0.x, b0.y), p01 = make_float2(b0.z, b0.w);  \
        float2 p10 = make_float2(b1.x, b1.y), p11 = make_float2(b1.z, b1.w);  \
        fma2(acc[0][0], qa0.x, p00); fma2(acc[0][1], qa0.x, p01);             \
        fma2(acc[0][2], qa0.x, p10); fma2(acc[0][3], qa0.x, p11);             \
        fma2(acc[1][0], qa0.y, p00); fma2(acc[1][1], qa0.y, p01);             \
        fma2(acc[1][2], qa0.y, p10); fma2(acc[1][3], qa0.y, p11);             \
        fma2(acc[2][0], qa1.x, p00); fma2(acc[2][1], qa1.x, p01);             \
        fma2(acc[2][2], qa1.x, p10); fma2(acc[2][3], qa1.x, p11);             \
        fma2(acc[3][0], qa1.y, p00); fma2(acc[3][1], qa1.y, p01);             \
        fma2(acc[3][2], qa1.y, p10); fma2(acc[3][3], qa1.y, p11);             \
        fma2(acc[4][0], qa2.x, p00); fma2(acc[4][1], qa2.x, p01);             \
        fma2(acc[4][2], qa2.x, p10); fma2(acc[4][3], qa2.x, p11);             \
        fma2(acc[5][0], qa2.y, p00); fma2(acc[5][1], qa2.y, p01);             \
        fma2(acc[5][2], qa2.y, p10); fma2(acc[5][3], qa2.y, p11);             \
        fma2(acc[6][0], qa3.x, p00); fma2(acc[6][1], qa3.x, p01);             \
        fma2(acc[6][2], qa3.x, p10); fma2(acc[6][3], qa3.x, p11);             \
        fma2(acc[7][0], qa3.y, p00); fma2(acc[7][1], qa3.y, p01);             \
        fma2(acc[7][2], qa3.y, p10); fma2(acc[7][3], qa3.y, p11);             \
    }

#define MMA_KK_DUP(AsBuf, BsBuf)                                              \
    _Pragma("unroll")                                                         \
    for (int kk = 0; kk < BK; kk++) {                                         \
        ulonglong2 qa0 = *(const ulonglong2*)&AsBuf[kk][2 * ty8];             \
        ulonglong2 qa1 = *(const ulonglong2*)&AsBuf[kk][2 * ty8 + 4];         \
        ulonglong2 qa2 = *(const ulonglong2*)&AsBuf[kk][2 * ty8 + 8];         \
        ulonglong2 qa3 = *(const ulonglong2*)&AsBuf[kk][2 * ty8 + 12];        \
        float4 b0 = *(const float4*)&BsBuf[kk][tx4];                          \
        float4 b1 = *(const float4*)&BsBuf[kk][tx4 + 64];                     \
        MMA_STEP_DUP(acc, qa0, qa1, qa2, qa3, b0, b1)                         \
    }

#define STAGE_A_DUP(AsBuf, va)                                                \
    _Pragma("unroll")                                                         \
    for (int q = 0; q < 8; q++)                                               \
        *(float2*)&AsBuf[ak + q][2 * ar] = make_float2(va[q], va[q]);

// ---------- fc1: [32768,256] x [256,1024] + exact GELU -----------------------
__global__ __launch_bounds__(256, 2)
void k_fc1(const float* __restrict__ A, const float* __restrict__ Wm,
           const float* __restrict__ bias, float* __restrict__ Out) {
    __shared__ float As[2][BK][ALDA];
    __shared__ float Bs[2][BK][BN + BPAD];
    const int K = 256, N = 1024;
    int t = threadIdx.x;
    int tx4 = (t & 15) * 4, ty8 = (t >> 4) * 8;
    int rowBase = blockIdx.y * BM, colBase = blockIdx.x * BN;
    int ar = t >> 1, ak = (t & 1) * 8;
    int bk = t >> 4, bn = (t & 15) * 4;
    const float* Ap = A + (size_t)(rowBase + ar) * K + ak;
    const float* Bp = Wm + (size_t)bk * N + colBase + bn;
    float2 acc[8][4];
    #pragma unroll
    for (int i = 0; i < 8; i++)
        #pragma unroll
        for (int j = 0; j < 4; j++) acc[i][j] = make_float2(0.f, 0.f);
    {
        float4 ra0 = *(const float4*)(Ap);
        float4 ra1 = *(const float4*)(Ap + 4);
        float va[8] = {ra0.x, ra0.y, ra0.z, ra0.w, ra1.x, ra1.y, ra1.z, ra1.w};
        STAGE_A_DUP(As[0], va)
        *(float4*)&Bs[0][bk][bn]      = *(const float4*)(Bp);
        *(float4*)&Bs[0][bk][bn + 64] = *(const float4*)(Bp + 64);
    }
    __syncthreads();
    const int nk = K / BK;
    #pragma unroll 1
    for (int kt = 0; kt < nk; kt++) {
        int cur = kt & 1;
        float4 ra0, ra1, rb0, rb1;
        bool more = (kt + 1 < nk);
        if (more) {
            ra0 = *(const float4*)(Ap + (kt + 1) * BK);
            ra1 = *(const float4*)(Ap + (kt + 1) * BK + 4);
            rb0 = *(const float4*)(Bp + (size_t)(kt + 1) * BK * N);
            rb1 = *(const float4*)(Bp + (size_t)(kt + 1) * BK * N + 64);
        }
        MMA_KK_DUP(As[cur], Bs[cur])
        if (more) {
            int nb = cur ^ 1;
            float va[8] = {ra0.x, ra0.y, ra0.z, ra0.w, ra1.x, ra1.y, ra1.z, ra1.w};
            STAGE_A_DUP(As[nb], va)
            *(float4*)&Bs[nb][bk][bn]      = rb0;
            *(float4*)&Bs[nb][bk][bn + 64] = rb1;
        }
        __syncthreads();
    }
    float4 bi0 = *(const float4*)(bias + colBase + tx4);
    float4 bi1 = *(const float4*)(bias + colBase + tx4 + 64);
    float bb[8] = {bi0.x, bi0.y, bi0.z, bi0.w, bi1.x, bi1.y, bi1.z, bi1.w};
    #pragma unroll
    for (int i = 0; i < 8; i++) {
        float v[8] = {acc[i][0].x, acc[i][0].y, acc[i][1].x, acc[i][1].y,
                      acc[i][2].x, acc[i][2].y, acc[i][3].x, acc[i][3].y};
        float o[8];
        #pragma unroll
        for (int j = 0; j < 8; j++) {
            float y = __fadd_rn(v[j], bb[j]);
            float e = erff(__fdiv_rn(y, 1.4142135623730951f));
            o[j] = 0.5f * __fmul_rn(y, __fadd_rn(e, 1.0f));
        }
        float* dst = Out + (size_t)(rowBase + ty8 + i) * N + colBase + tx4;
        *(float4*)dst        = make_float4(o[0], o[1], o[2], o[3]);
        *(float4*)(dst + 64) = make_float4(o[4], o[5], o[6], o[7]);
    }
}

__global__ void k_grn_sumsq(const float* __restrict__ C, float* __restrict__ S) {
    __shared__ float sm[32][33];
    int b = blockIdx.y;
    int c = blockIdx.x * 32 + threadIdx.x;
    int ty = threadIdx.y;
    const float* base = C + ((long)b << 12) * 1024 + c;
    float acc = 0.0f;
    for (int tt = 0; tt < 128; tt++) {
        float v = base[(ty + (tt << 5)) * 1024];
        acc = __fadd_rn(acc, __fmul_rn(v, v));
    }
    sm[ty][threadIdx.x] = acc;
    __syncthreads();
    #pragma unroll
    for (int off = 16; off > 0; off >>= 1) {
        if (ty < off)
            sm[ty][threadIdx.x] = __fadd_rn(sm[ty][threadIdx.x], sm[ty + off][threadIdx.x]);
        __syncthreads();
    }
    if (ty == 0) S[b * 1024 + c] = sm[0][threadIdx.x];
}

__global__ void k_grn_nx(const float* __restrict__ S, float* __restrict__ nxo) {
    __shared__ float s[40];
    int b = blockIdx.x, t = threadIdx.x, w = t >> 5, l = t & 31;
    float gx = sqrtf(S[b * 1024 + t]);
    float ws = warp_red(gx);
    if (l == 0) s[w] = ws;
    __syncthreads();
    if (w == 0) {
        float p = warp_red(s[l]);
        if (l == 0) s[33] = p;
    }
    __syncthreads();
    float mean = __fmul_rn(s[33], 0.0009765625f);
    nxo[b * 1024 + t] = __fdiv_rn(gx, __fadd_rn(mean, 1e-6f));
}

__device__ __forceinline__ void grn_chain8(float* ra, const float* nxp,
                                           const float* ggp, const float* gbp) {
    float4 n0 = *(const float4*)(nxp), n1 = *(const float4*)(nxp + 4);
    float4 g0 = *(const float4*)(ggp), g1 = *(const float4*)(ggp + 4);
    float4 h0 = *(const float4*)(gbp), h1 = *(const float4*)(gbp + 4);
    float nn[8] = {n0.x,n0.y,n0.z,n0.w,n1.x,n1.y,n1.z,n1.w};
    float gG[8] = {g0.x,g0.y,g0.z,g0.w,g1.x,g1.y,g1.z,g1.w};
    float gB[8] = {h0.x,h0.y,h0.z,h0.w,h1.x,h1.y,h1.z,h1.w};
    #pragma unroll
    for (int q = 0; q < 8; q++) {
        float t1 = __fmul_rn(ra[q], nn[q]);
        t1 = __fmul_rn(gG[q], t1);
        t1 = __fadd_rn(t1, gB[q]);
        ra[q] = __fadd_rn(t1, ra[q]);
    }
}

// ---------- fc2: [32768,1024] x [1024,256], GRN at A-load --------------------
__global__ __launch_bounds__(256, 2)
void k_fc2(const float* __restrict__ A, const float* __restrict__ Wm,
           const float* __restrict__ nx, const float* __restrict__ gg,
           const float* __restrict__ gb, const float* __restrict__ b2,
           const float* __restrict__ res, float* __restrict__ Out) {
    __shared__ float As[2][BK][ALDA];
    __shared__ float Bs[2][BK][BN + BPAD];
    const int K = 1024, N = 256;
    int t = threadIdx.x;
    int tx4 = (t & 15) * 4, ty8 = (t >> 4) * 8;
    int rowBase = blockIdx.y * BM, colBase = blockIdx.x * BN;
    int bidx = rowBase >> 12;
    int ar = t >> 1, ak = (t & 1) * 8;
    int bk = t >> 4, bn = (t & 15) * 4;
    const float* Ap  = A + (size_t)(rowBase + ar) * K + ak;
    const float* Bp  = Wm + (size_t)bk * N + colBase + bn;
    const float* nxp = nx + bidx * 1024 + ak;
    const float* ggp = gg + ak;
    const float* gbp = gb + ak;
    float2 acc[8][4];
    #pragma unroll
    for (int i = 0; i < 8; i++)
        #pragma unroll
        for (int j = 0; j < 4; j++) acc[i][j] = make_float2(0.f, 0.f);
    {
        float va[8];
        float4 v0 = *(const float4*)(Ap), v1 = *(const float4*)(Ap + 4);
        va[0]=v0.x; va[1]=v0.y; va[2]=v0.z; va[3]=v0.w;
        va[4]=v1.x; va[5]=v1.y; va[6]=v1.z; va[7]=v1.w;
        grn_chain8(va, nxp, ggp, gbp);
        STAGE_A_DUP(As[0], va)
        *(float4*)&Bs[0][bk][bn]      = *(const float4*)(Bp);
        *(float4*)&Bs[0][bk][bn + 64] = *(const float4*)(Bp + 64);
    }
    __syncthreads();
    const int nk = K / BK;
    #pragma unroll 1
    for (int kt = 0; kt < nk; kt++) {
        int cur = kt & 1;
        bool more = (kt + 1 < nk);
        float va[8];
        float4 rb0, rb1;
        if (more) {
            int ko = (kt + 1) * BK;
            float4 v0 = *(const float4*)(Ap + ko), v1 = *(const float4*)(Ap + ko + 4);
            va[0]=v0.x; va[1]=v0.y; va[2]=v0.z; va[3]=v0.w;
            va[4]=v1.x; va[5]=v1.y; va[6]=v1.z; va[7]=v1.w;
            grn_chain8(va, nxp + ko, ggp + ko, gbp + ko);
            rb0 = *(const float4*)(Bp + (size_t)ko * N);
            rb1 = *(const float4*)(Bp + (size_t)ko * N + 64);
        }
        MMA_KK_DUP(As[cur], Bs[cur])
        if (more) {
            int nb = cur ^ 1;
            STAGE_A_DUP(As[nb], va)
            *(float4*)&Bs[nb][bk][bn]      = rb0;
            *(float4*)&Bs[nb][bk][bn + 64] = rb1;
        }
        __syncthreads();
    }
    float4 bi0 = *(const float4*)(b2 + colBase + tx4);
    float4 bi1 = *(const float4*)(b2 + colBase + tx4 + 64);
    float bb[8] = {bi0.x, bi0.y, bi0.z, bi0.w, bi1.x, bi1.y, bi1.z, bi1.w};
    #pragma unroll
    for (int i = 0; i < 8; i++) {
        size_t off = (size_t)(rowBase + ty8 + i) * N + colBase + tx4;
        float4 r0 = *(const float4*)(res + off);
        float4 r1 = *(const float4*)(res + off + 64);
        float rr[8] = {r0.x, r0.y, r0.z, r0.w, r1.x, r1.y, r1.z, r1.w};
        float v[8] = {acc[i][0].x, acc[i][0].y, acc[i][1].x, acc[i][1].y,
                      acc[i][2].x, acc[i][2].y, acc[i][3].x, acc[i][3].y};
        float o[8];
        #pragma unroll
        for (int j = 0; j < 8; j++)
            o[j] = __fadd_rn(__fadd_rn(v[j], bb[j]), rr[j]);
        *(float4*)(Out + off)      = make_float4(o[0], o[1], o[2], o[3]);
        *(float4*)(Out + off + 64) = make_float4(o[4], o[5], o[6], o[7]);
    }
}

__global__ __launch_bounds__(256)
void k_rownorm_w(const float* __restrict__ X, float* __restrict__ R) {
    int n = blockIdx.x * 8 + (threadIdx.x >> 5);
    int l = threadIdx.x & 31;
    const float* xp = X + (size_t)n * 256 + l;
    float si[8];
    #pragma unroll
    for (int i = 0; i < 8; i++) {
        float v = xp[i * 32];
        si[i] = warp_red(__fmul_rn(v, v));
    }
    float s = combine8(si);
    if (l == 0) R[n] = s;
}

// ---------- VQ: scores GEMM + argmin ------------------------------------------
__global__ __launch_bounds__(256, 2)
void k_vq(const float* __restrict__ A, const float* __restrict__ CB,
          const float* __restrict__ rr, const float* __restrict__ cn,
          ull* __restrict__ best) {
    __shared__ float As[2][BK][ALDA];
    __shared__ float Bs[2][BK][BN + BPAD];
    __shared__ ull sbest[BM];
    const int K = 256;
    int t = threadIdx.x;
    int tx4 = (t & 15) * 4, ty8 = (t >> 4) * 8;
    int rowBase = blockIdx.y * BM, colBase = blockIdx.x * BN;
    int ar = t >> 1, ak = (t & 1) * 8;
    int lc = t >> 1, kd = (t & 1) * 8;
    if (t < BM) sbest[t] = ~0ull;
    const float* Ap = A + (size_t)(rowBase + ar) * K + ak;
    const float* Cp = CB + (size_t)(colBase + lc) * K + kd;
    float2 acc[8][4];
    #pragma unroll
    for (int i = 0; i < 8; i++)
        #pragma unroll
        for (int j = 0; j < 4; j++) acc[i][j] = make_float2(0.f, 0.f);
    {
        float4 ra0 = *(const float4*)(Ap);
        float4 ra1 = *(const float4*)(Ap + 4);
        float va[8] = {ra0.x, ra0.y, ra0.z, ra0.w, ra1.x, ra1.y, ra1.z, ra1.w};
        STAGE_A_DUP(As[0], va)
        float4 rb0 = *(const float4*)(Cp);
        float4 rb1 = *(const float4*)(Cp + 4);
        Bs[0][kd + 0][lc] = rb0.x; Bs[0][kd + 1][lc] = rb0.y;
        Bs[0][kd + 2][lc] = rb0.z; Bs[0][kd + 3][lc] = rb0.w;
        Bs[0][kd + 4][lc] = rb1.x; Bs[0][kd + 5][lc] = rb1.y;
        Bs[0][kd + 6][lc] = rb1.z; Bs[0][kd + 7][lc] = rb1.w;
    }
    __syncthreads();
    const int nk = K / BK;
    #pragma unroll 1
    for (int kt = 0; kt < nk; kt++) {
        int cur = kt & 1;
        bool more = (kt + 1 < nk);
        float4 ra0, ra1, rb0, rb1;
        if (more) {
            ra0 = *(const float4*)(Ap + (kt + 1) * BK);
            ra1 = *(const float4*)(Ap + (kt + 1) * BK + 4);
            rb0 = *(const float4*)(Cp + (kt + 1) * BK);
            rb1 = *(const float4*)(Cp + (kt + 1) * BK + 4);
        }
        MMA_KK_DUP(As[cur], Bs[cur])
        if (more) {
            int nb = cur ^ 1;
            float va[8] = {ra0.x, ra0.y, ra0.z, ra0.w, ra1.x, ra1.y, ra1.z, ra1.w};
            STAGE_A_DUP(As[nb], va)
            Bs[nb][kd + 0][lc] = rb0.x; Bs[nb][kd + 1][lc] = rb0.y;
            Bs[nb][kd + 2][lc] = rb0.z; Bs[nb][kd + 3][lc] = rb0.w;
            Bs[nb][kd + 4][lc] = rb1.x; Bs[nb][kd + 5][lc] = rb1.y;
            Bs[nb][kd + 6][lc] = rb1.z; Bs[nb][kd + 7][lc] = rb1.w;
        }
        __syncthreads();
    }
    float4 c0 = *(const float4*)(cn + colBase + tx4);
    float4 c1 = *(const float4*)(cn + colBase + tx4 + 64);
    float cc[8] = {c0.x, c0.y, c0.z, c0.w, c1.x, c1.y, c1.z, c1.w};
    int codes[8];
    #pragma unroll
    for (int j = 0; j < 4; j++) { codes[j] = colBase + tx4 + j; codes[4 + j] = colBase + tx4 + 64 + j; }
    #pragma unroll
    for (int i = 0; i < 8; i++) {
        float rrow = rr[rowBase + ty8 + i];
        float v[8] = {acc[i][0].x, acc[i][0].y, acc[i][1].x, acc[i][1].y,
                      acc[i][2].x, acc[i][2].y, acc[i][3].x, acc[i][3].y};
        ull mykey = ~0ull;
        #pragma unroll
        for (int j = 0; j < 8; j++) {
            float m2 = __fmul_rn(2.0f, v[j]);
            float t1 = __fsub_rn(rrow, m2);
            float d2 = __fadd_rn(t1, cc[j]);
            ull key = ((ull)__float_as_uint(d2) << 32) | (unsigned)codes[j];
            if (key < mykey) mykey = key;
        }
        atomicMin(&sbest[ty8 + i], mykey);
    }
    __syncthreads();
    if (t < BM) atomicMin(&best[rowBase + t], sbest[t]);
}

__global__ void k_vq_gather(const ull* __restrict__ best, const float* __restrict__ CB,
                            const float* __restrict__ enc, float* __restrict__ qn,
                            float* __restrict__ out_idx) {
    int n = blockIdx.x, c = threadIdx.x;
    int k = (int)(unsigned)(best[n] & 0xFFFFFFFFull);
    float q = CB[k * 256 + c];
    float inp = enc[n * 256 + c];
    qn[n * 256 + c] = __fsub_rn(__fadd_rn(q, inp), inp);
    if (c == 0) out_idx[n] = (float)k;
}

// ---------------- host side ---------------------------------------------------
static void run_block(const float* cur, float* nxt, const float* const* p, int off, int d,
                      float* LN, float* Cbuf, float* grn, float* nx, float* cwT) {
    const float* cw  = p[off + 0] + d * 256 * 49;
    const float* cbi = p[off + 1] + d * 256;
    const float* lng = p[off + 2] + d * 256;
    const float* lnb = p[off + 3] + d * 256;
    const float* w1  = p[off + 4] + d * 256 * 1024;
    const float* b1  = p[off + 5] + d * 1024;
    const float* gg  = p[off + 6] + d * 1024;
    const float* gb  = p[off + 7] + d * 1024;
    const float* w2  = p[off + 8] + d * 1024 * 256;
    const float* b2  = p[off + 9] + d * 256;
    k_wtrans<<<49, 256>>>(cw, cwT);
    k_conv_ln<<<NROW / 32, 256>>>(cur, LN, cwT, cbi, lng, lnb);
    k_fc1<<<dim3(INTER / BN, NROW / BM), 256>>>(LN, w1, b1, Cbuf);
    k_grn_sumsq<<<dim3(32, 8), dim3(32, 32)>>>(Cbuf, grn);
    k_grn_nx<<<BB, 1024>>>(grn, nx);
    k_fc2<<<dim3(CC / BN, NROW / BM), 256>>>(Cbuf, w2, nx, gg, gb, b2, cur, nxt);
}

extern "C" void kernel_launch(void* const* d_in, const int* in_sizes, int n_in,
                              void* d_out, int out_size) {
    const float* x  = (const float*)d_in[0];
    const float* cb = (const float*)d_in[1];
    const float* p[20];
    for (int i = 0; i < 20; i++) p[i] = (const float*)d_in[2 + i];
    float* out = (float*)d_out;

    float *A0, *A1, *LN, *Cbuf, *grn, *nx, *rr, *cn, *cwT;
    ull* best;
    cudaGetSymbolAddress((void**)&A0,   g_A0);
    cudaGetSymbolAddress((void**)&A1,   g_A1);
    cudaGetSymbolAddress((void**)&LN,   g_LN);
    cudaGetSymbolAddress((void**)&Cbuf, g_C);
    cudaGetSymbolAddress((void**)&grn,  g_grn);
    cudaGetSymbolAddress((void**)&nx,   g_scl);
    cudaGetSymbolAddress((void**)&rr,   g_r);
    cudaGetSymbolAddress((void**)&cn,   g_cn);
    cudaGetSymbolAddress((void**)&best, g_best);
    cudaGetSymbolAddress((void**)&cwT,  g_cwT);

    dim3 tt(32, 8);
    k_rownorm_w<<<KCB / 8, 256>>>(cb, cn);
    k_transpose<<<dim3(128, 8, 8), tt>>>(x, A0, 256, 4096);

    float* cur = A0;
    float* nxt = A1;
    for (int d = 0; d < 2; d++) {
        run_block(cur, nxt, p, 0, d, LN, Cbuf, grn, nx, cwT);
        float* tmp = cur; cur = nxt; nxt = tmp;
    }
    k_rownorm_w<<<NROW / 8, 256>>>(cur, rr);
    cudaMemsetAsync(best, 0xFF, NROW * sizeof(ull));
    k_vq<<<dim3(KCB / BN, NROW / BM), 256>>>(cur, cb, rr, cn, best);
    k_vq_gather<<<NROW, 256>>>(best, cb, cur, nxt, out + 2 * NROW * CC);
    k_transpose<<<dim3(8, 128, 8), tt>>>(nxt, out, 4096, 256);
    cur = nxt;
    nxt = (cur == A0) ? A1 : A0;
    for (int d = 0; d < 2; d++) {
        run_block(cur, nxt, p, 10, d, LN, Cbuf, grn, nx, cwT);
        float* tmp = cur; cur = nxt; nxt = tmp;
    }
    k_transpose<<<dim3(8, 128, 8), tt>>>(cur, out + NROW * CC, 4096, 256);
}

// round 15
// speedup vs baseline: 1.2254x; 1.2254x over previous
#include <cuda_runtime.h>
#include <math.h>
#include <stdint.h>

#define BB    8
#define CC    256
#define NROW  32768
#define INTER 1024
#define KCB   1024

typedef unsigned long long ull;

__device__ float g_A0[NROW * CC];
__device__ float g_A1[NROW * CC];
__device__ float g_LN[NROW * CC];
__device__ float g_C [NROW * INTER];
__device__ float g_grn[BB * INTER];
__device__ float g_scl[BB * INTER];
__device__ float g_r [NROW];
__device__ float g_cn[KCB];
__device__ ull   g_best[NROW];
__device__ float g_cwT[49 * CC];

__device__ __forceinline__ ull dup2(float a) {
    ull r; asm("mov.b64 %0, {%1, %1};" : "=l"(r) : "f"(a)); return r;
}
__device__ __forceinline__ void fma2(float2& d, ull a2, const float2& b) {
    ull& dd = reinterpret_cast<ull&>(d);
    asm("fma.rn.f32x2 %0, %1, %2, %0;" : "+l"(dd)
        : "l"(a2), "l"(reinterpret_cast<const ull&>(b)));
}
__device__ __forceinline__ float warp_red(float v) {
    #pragma unroll
    for (int off = 16; off > 0; off >>= 1)
        v = __fadd_rn(v, __shfl_down_sync(0xffffffffu, v, off));
    return v;
}
__device__ __forceinline__ float combine8(const float* si) {
    float t0 = __fadd_rn(si[0], si[4]);
    float t1 = __fadd_rn(si[1], si[5]);
    float t2 = __fadd_rn(si[2], si[6]);
    float t3 = __fadd_rn(si[3], si[7]);
    return __fadd_rn(__fadd_rn(t0, t2), __fadd_rn(t1, t3));
}

__global__ void k_transpose(const float* __restrict__ in, float* __restrict__ out,
                            int R, int S) {
    __shared__ float tile[32][33];
    int b = blockIdx.z;
    int base = b * R * S;
    int s0 = blockIdx.x * 32, r0 = blockIdx.y * 32;
    int sx = s0 + threadIdx.x;
    for (int i = threadIdx.y; i < 32; i += 8)
        tile[i][threadIdx.x] = in[base + (r0 + i) * S + sx];
    __syncthreads();
    int rx = r0 + threadIdx.x;
    for (int i = threadIdx.y; i < 32; i += 8)
        out[base + (s0 + i) * R + rx] = tile[threadIdx.x][i];
}

__global__ void k_wtrans(const float* __restrict__ cw, float* __restrict__ cwT) {
    cwT[blockIdx.x * CC + threadIdx.x] = cw[threadIdx.x * 49 + blockIdx.x];
}

// ---------- depthwise conv 7x7 + bias + LayerNorm: 4x8-pixel 2D tile ---------
__global__ __launch_bounds__(256)
void k_conv_ln(const float* __restrict__ in, float* __restrict__ out,
               const float* __restrict__ cwT, const float* __restrict__ cb,
               const float* __restrict__ lng, const float* __restrict__ lnb) {
    __shared__ float spart[2][32][8];
    int g = threadIdx.x >> 5, l = threadIdx.x & 31, c = g * 32 + l;
    int idx = blockIdx.x;
    int b  = idx >> 7;
    int tile = idx & 127;
    int h0 = (tile >> 3) * 4;
    int w0 = (tile & 7) * 8;
    const float* base = in + ((long)b << 12) * CC;

    bool validw[14];
    #pragma unroll
    for (int j = 0; j < 14; j++) validw[j] = ((unsigned)(w0 + j - 3) < 64u);

    float acc[32];
    #pragma unroll
    for (int p = 0; p < 32; p++) acc[p] = 0.0f;

    #pragma unroll
    for (int ih = 0; ih < 10; ih++) {
        int hh = h0 + ih - 3;
        if ((unsigned)hh >= 64u) continue;
        const float* xrow = base + ((size_t)(hh << 6)) * CC + c;
        float xv[14];
        #pragma unroll
        for (int j = 0; j < 14; j++)
            xv[j] = validw[j] ? xrow[(w0 + j - 3) * CC] : 0.0f;
        #pragma unroll
        for (int kh = 0; kh < 7; kh++) {
            int ph = ih - kh;
            if (ph < 0 || ph > 3) continue;
            float wv[7];
            #pragma unroll
            for (int kw = 0; kw < 7; kw++)
                wv[kw] = cwT[(kh * 7 + kw) * CC + c];
            #pragma unroll
            for (int pw = 0; pw < 8; pw++)
                #pragma unroll
                for (int kw = 0; kw < 7; kw++)
                    if (validw[pw + kw])
                        acc[ph * 8 + pw] = __fmaf_rn(wv[kw], xv[pw + kw], acc[ph * 8 + pw]);
        }
    }

    float biasv = cb[c];
    #pragma unroll
    for (int p = 0; p < 32; p++) acc[p] = __fadd_rn(acc[p], biasv);

    #pragma unroll
    for (int p = 0; p < 32; p++) {
        float s = warp_red(acc[p]);
        if (l == 0) spart[0][p][g] = s;
    }
    __syncthreads();
    #pragma unroll
    for (int p = 0; p < 32; p++) {
        float mu = __fmul_rn(combine8(&spart[0][p][0]), 0.00390625f);
        acc[p] = __fsub_rn(acc[p], mu);
    }
    #pragma unroll
    for (int p = 0; p < 32; p++) {
        float s = warp_red(__fmul_rn(acc[p], acc[p]));
        if (l == 0) spart[1][p][g] = s;
    }
    __syncthreads();

    float gv = lng[c], bv = lnb[c];
    #pragma unroll
    for (int p = 0; p < 32; p++) {
        float var = __fmul_rn(combine8(&spart[1][p][0]), 0.00390625f);
        float rs = rsqrtf(__fadd_rn(var, 1e-5f));
        int gp = (b << 12) + ((h0 + (p >> 3)) << 6) + w0 + (p & 7);
        out[(size_t)gp * CC + c] =
            __fadd_rn(__fmul_rn(__fmul_rn(acc[p], rs), gv), bv);
    }
}

// ---------- fp32 GEMM core (all GEMMs, bit-exact, proven) --------------------
#define BM 128
#define BN 128
#define BK 16
#define APAD 4
#define BPAD 4

#define MMA_STEP(acc, a0, a1, b0, b1)                                         \
    {                                                                         \
        float2 p00 = make_float2(b0.x, b0.y), p01 = make_float2(b0.z, b0.w);  \
        float2 p10 = make_float2(b1.x, b1.y), p11 = make_float2(b1.z, b1.w);  \
        ull ap;                                                               \
        ap = dup2(a0.x); fma2(acc[0][0], ap, p00); fma2(acc[0][1], ap, p01);  \
                         fma2(acc[0][2], ap, p10); fma2(acc[0][3], ap, p11);  \
        ap = dup2(a0.y); fma2(acc[1][0], ap, p00); fma2(acc[1][1], ap, p01);  \
                         fma2(acc[1][2], ap, p10); fma2(acc[1][3], ap, p11);  \
        ap = dup2(a0.z); fma2(acc[2][0], ap, p00); fma2(acc[2][1], ap, p01);  \
                         fma2(acc[2][2], ap, p10); fma2(acc[2][3], ap, p11);  \
        ap = dup2(a0.w); fma2(acc[3][0], ap, p00); fma2(acc[3][1], ap, p01);  \
                         fma2(acc[3][2], ap, p10); fma2(acc[3][3], ap, p11);  \
        ap = dup2(a1.x); fma2(acc[4][0], ap, p00); fma2(acc[4][1], ap, p01);  \
                         fma2(acc[4][2], ap, p10); fma2(acc[4][3], ap, p11);  \
        ap = dup2(a1.y); fma2(acc[5][0], ap, p00); fma2(acc[5][1], ap, p01);  \
                         fma2(acc[5][2], ap, p10); fma2(acc[5][3], ap, p11);  \
        ap = dup2(a1.z); fma2(acc[6][0], ap, p00); fma2(acc[6][1], ap, p01);  \
                         fma2(acc[6][2], ap, p10); fma2(acc[6][3], ap, p11);  \
        ap = dup2(a1.w); fma2(acc[7][0], ap, p00); fma2(acc[7][1], ap, p01);  \
                         fma2(acc[7][2], ap, p10); fma2(acc[7][3], ap, p11);  \
    }

__global__ __launch_bounds__(256, 2)
void k_fc1(const float* __restrict__ A, const float* __restrict__ Wm,
           const float* __restrict__ bias, float* __restrict__ Out) {
    __shared__ float As[2][BK][BM + APAD];
    __shared__ float Bs[2][BK][BN + BPAD];
    const int K = 256, N = 1024;
    int t = threadIdx.x;
    int tx4 = (t & 15) * 4, ty8 = (t >> 4) * 8;
    int rowBase = blockIdx.y * BM, colBase = blockIdx.x * BN;
    int ar = t >> 1, ak = (t & 1) * 8;
    int bk = t >> 4, bn = (t & 15) * 4;
    const float* Ap = A + (size_t)(rowBase + ar) * K + ak;
    const float* Bp = Wm + (size_t)bk * N + colBase + bn;
    float2 acc[8][4];
    #pragma unroll
    for (int i = 0; i < 8; i++)
        #pragma unroll
        for (int j = 0; j < 4; j++) acc[i][j] = make_float2(0.f, 0.f);
    {
        float4 ra0 = *(const float4*)(Ap);
        float4 ra1 = *(const float4*)(Ap + 4);
        As[0][ak + 0][ar] = ra0.x; As[0][ak + 1][ar] = ra0.y;
        As[0][ak + 2][ar] = ra0.z; As[0][ak + 3][ar] = ra0.w;
        As[0][ak + 4][ar] = ra1.x; As[0][ak + 5][ar] = ra1.y;
        As[0][ak + 6][ar] = ra1.z; As[0][ak + 7][ar] = ra1.w;
        *(float4*)&Bs[0][bk][bn]      = *(const float4*)(Bp);
        *(float4*)&Bs[0][bk][bn + 64] = *(const float4*)(Bp + 64);
    }
    __syncthreads();
    const int nk = K / BK;
    #pragma unroll 1
    for (int kt = 0; kt < nk; kt++) {
        int cur = kt & 1;
        float4 ra0, ra1, rb0, rb1;
        bool more = (kt + 1 < nk);
        if (more) {
            ra0 = *(const float4*)(Ap + (kt + 1) * BK);
            ra1 = *(const float4*)(Ap + (kt + 1) * BK + 4);
            rb0 = *(const float4*)(Bp + (size_t)(kt + 1) * BK * N);
            rb1 = *(const float4*)(Bp + (size_t)(kt + 1) * BK * N + 64);
        }
        #pragma unroll
        for (int kk = 0; kk < BK; kk++) {
            float4 a0 = *(const float4*)&As[cur][kk][ty8];
            float4 a1 = *(const float4*)&As[cur][kk][ty8 + 4];
            float4 b0 = *(const float4*)&Bs[cur][kk][tx4];
            float4 b1 = *(const float4*)&Bs[cur][kk][tx4 + 64];
            MMA_STEP(acc, a0, a1, b0, b1)
        }
        if (more) {
            int nb = cur ^ 1;
            As[nb][ak + 0][ar] = ra0.x; As[nb][ak + 1][ar] = ra0.y;
            As[nb][ak + 2][ar] = ra0.z; As[nb][ak + 3][ar] = ra0.w;
            As[nb][ak + 4][ar] = ra1.x; As[nb][ak + 5][ar] = ra1.y;
            As[nb][ak + 6][ar] = ra1.z; As[nb][ak + 7][ar] = ra1.w;
            *(float4*)&Bs[nb][bk][bn]      = rb0;
            *(float4*)&Bs[nb][bk][bn + 64] = rb1;
        }
        __syncthreads();
    }
    float4 bi0 = *(const float4*)(bias + colBase + tx4);
    float4 bi1 = *(const float4*)(bias + colBase + tx4 + 64);
    float bb[8] = {bi0.x, bi0.y, bi0.z, bi0.w, bi1.x, bi1.y, bi1.z, bi1.w};
    #pragma unroll
    for (int i = 0; i < 8; i++) {
        float v[8] = {acc[i][0].x, acc[i][0].y, acc[i][1].x, acc[i][1].y,
                      acc[i][2].x, acc[i][2].y, acc[i][3].x, acc[i][3].y};
        float o[8];
        #pragma unroll
        for (int j = 0; j < 8; j++) {
            float y = __fadd_rn(v[j], bb[j]);
            float e = erff(__fdiv_rn(y, 1.4142135623730951f));
            o[j] = 0.5f * __fmul_rn(y, __fadd_rn(e, 1.0f));
        }
        float* dst = Out + (size_t)(rowBase + ty8 + i) * N + colBase + tx4;
        *(float4*)dst        = make_float4(o[0], o[1], o[2], o[3]);
        *(float4*)(dst + 64) = make_float4(o[4], o[5], o[6], o[7]);
    }
}

__global__ void k_grn_sumsq(const float* __restrict__ C, float* __restrict__ S) {
    __shared__ float sm[32][33];
    int b = blockIdx.y;
    int c = blockIdx.x * 32 + threadIdx.x;
    int ty = threadIdx.y;
    const float* base = C + ((long)b << 12) * 1024 + c;
    float acc = 0.0f;
    for (int tt = 0; tt < 128; tt++) {
        float v = base[(ty + (tt << 5)) * 1024];
        acc = __fadd_rn(acc, __fmul_rn(v, v));
    }
    sm[ty][threadIdx.x] = acc;
    __syncthreads();
    #pragma unroll
    for (int off = 16; off > 0; off >>= 1) {
        if (ty < off)
            sm[ty][threadIdx.x] = __fadd_rn(sm[ty][threadIdx.x], sm[ty + off][threadIdx.x]);
        __syncthreads();
    }
    if (ty == 0) S[b * 1024 + c] = sm[0][threadIdx.x];
}

__global__ void k_grn_nx(const float* __restrict__ S, float* __restrict__ nxo) {
    __shared__ float s[40];
    int b = blockIdx.x, t = threadIdx.x, w = t >> 5, l = t & 31;
    float gx = sqrtf(S[b * 1024 + t]);
    float ws = warp_red(gx);
    if (l == 0) s[w] = ws;
    __syncthreads();
    if (w == 0) {
        float p = warp_red(s[l]);
        if (l == 0) s[33] = p;
    }
    __syncthreads();
    float mean = __fmul_rn(s[33], 0.0009765625f);
    nxo[b * 1024 + t] = __fdiv_rn(gx, __fadd_rn(mean, 1e-6f));
}

__device__ __forceinline__ void grn_chain8(float* ra, const float* nxp,
                                           const float* ggp, const float* gbp) {
    float4 n0 = *(const float4*)(nxp), n1 = *(const float4*)(nxp + 4);
    float4 g0 = *(const float4*)(ggp), g1 = *(const float4*)(ggp + 4);
    float4 h0 = *(const float4*)(gbp), h1 = *(const float4*)(gbp + 4);
    float nn[8] = {n0.x,n0.y,n0.z,n0.w,n1.x,n1.y,n1.z,n1.w};
    float gG[8] = {g0.x,g0.y,g0.z,g0.w,g1.x,g1.y,g1.z,g1.w};
    float gB[8] = {h0.x,h0.y,h0.z,h0.w,h1.x,h1.y,h1.z,h1.w};
    #pragma unroll
    for (int q = 0; q < 8; q++) {
        float t1 = __fmul_rn(ra[q], nn[q]);
        t1 = __fmul_rn(gG[q], t1);
        t1 = __fadd_rn(t1, gB[q]);
        ra[q] = __fadd_rn(t1, ra[q]);
    }
}

__global__ __launch_bounds__(256, 2)
void k_fc2(const float* __restrict__ A, const float* __restrict__ Wm,
           const float* __restrict__ nx, const float* __restrict__ gg,
           const float* __restrict__ gb, const float* __restrict__ b2,
           const float* __restrict__ res, float* __restrict__ Out) {
    __shared__ float As[2][BK][BM + APAD];
    __shared__ float Bs[2][BK][BN + BPAD];
    const int K = 1024, N = 256;
    int t = threadIdx.x;
    int tx4 = (t & 15) * 4, ty8 = (t >> 4) * 8;
    int rowBase = blockIdx.y * BM, colBase = blockIdx.x * BN;
    int bidx = rowBase >> 12;
    int ar = t >> 1, ak = (t & 1) * 8;
    int bk = t >> 4, bn = (t & 15) * 4;
    const float* Ap  = A + (size_t)(rowBase + ar) * K + ak;
    const float* Bp  = Wm + (size_t)bk * N + colBase + bn;
    const float* nxp = nx + bidx * 1024 + ak;
    const float* ggp = gg + ak;
    const float* gbp = gb + ak;
    float2 acc[8][4];
    #pragma unroll
    for (int i = 0; i < 8; i++)
        #pragma unroll
        for (int j = 0; j < 4; j++) acc[i][j] = make_float2(0.f, 0.f);
    {
        float ra[8];
        float4 v0 = *(const float4*)(Ap), v1 = *(const float4*)(Ap + 4);
        ra[0]=v0.x; ra[1]=v0.y; ra[2]=v0.z; ra[3]=v0.w;
        ra[4]=v1.x; ra[5]=v1.y; ra[6]=v1.z; ra[7]=v1.w;
        grn_chain8(ra, nxp, ggp, gbp);
        #pragma unroll
        for (int q = 0; q < 8; q++) As[0][ak + q][ar] = ra[q];
        *(float4*)&Bs[0][bk][bn]      = *(const float4*)(Bp);
        *(float4*)&Bs[0][bk][bn + 64] = *(const float4*)(Bp + 64);
    }
    __syncthreads();
    const int nk = K / BK;
    #pragma unroll 1
    for (int kt = 0; kt < nk; kt++) {
        int cur = kt & 1;
        bool more = (kt + 1 < nk);
        float ra[8];
        float4 rb0, rb1;
        if (more) {
            int ko = (kt + 1) * BK;
            float4 v0 = *(const float4*)(Ap + ko), v1 = *(const float4*)(Ap + ko + 4);
            ra[0]=v0.x; ra[1]=v0.y; ra[2]=v0.z; ra[3]=v0.w;
            ra[4]=v1.x; ra[5]=v1.y; ra[6]=v1.z; ra[7]=v1.w;
            grn_chain8(ra, nxp + ko, ggp + ko, gbp + ko);
            rb0 = *(const float4*)(Bp + (size_t)ko * N);
            rb1 = *(const float4*)(Bp + (size_t)ko * N + 64);
        }
        #pragma unroll
        for (int kk = 0; kk < BK; kk++) {
            float4 a0 = *(const float4*)&As[cur][kk][ty8];
            float4 a1 = *(const float4*)&As[cur][kk][ty8 + 4];
            float4 b0 = *(const float4*)&Bs[cur][kk][tx4];
            float4 b1 = *(const float4*)&Bs[cur][kk][tx4 + 64];
            MMA_STEP(acc, a0, a1, b0, b1)
        }
        if (more) {
            int nb = cur ^ 1;
            #pragma unroll
            for (int q = 0; q < 8; q++) As[nb][ak + q][ar] = ra[q];
            *(float4*)&Bs[nb][bk][bn]      = rb0;
            *(float4*)&Bs[nb][bk][bn + 64] = rb1;
        }
        __syncthreads();
    }
    float4 bi0 = *(const float4*)(b2 + colBase + tx4);
    float4 bi1 = *(const float4*)(b2 + colBase + tx4 + 64);
    float bb[8] = {bi0.x, bi0.y, bi0.z, bi0.w, bi1.x, bi1.y, bi1.z, bi1.w};
    #pragma unroll
    for (int i = 0; i < 8; i++) {
        size_t off = (size_t)(rowBase + ty8 + i) * N + colBase + tx4;
        float4 r0 = *(const float4*)(res + off);
        float4 r1 = *(const float4*)(res + off + 64);
        float rr[8] = {r0.x, r0.y, r0.z, r0.w, r1.x, r1.y, r1.z, r1.w};
        float v[8] = {acc[i][0].x, acc[i][0].y, acc[i][1].x, acc[i][1].y,
                      acc[i][2].x, acc[i][2].y, acc[i][3].x, acc[i][3].y};
        float o[8];
        #pragma unroll
        for (int j = 0; j < 8; j++)
            o[j] = __fadd_rn(__fadd_rn(v[j], bb[j]), rr[j]);
        *(float4*)(Out + off)      = make_float4(o[0], o[1], o[2], o[3]);
        *(float4*)(Out + off + 64) = make_float4(o[4], o[5], o[6], o[7]);
    }
}

// row sum-of-squares; optionally also initializes the argmin table (saves the
// separate 256 KB memset launch). Reduction identical to verified version.
__global__ __launch_bounds__(256)
void k_rownorm_w(const float* __restrict__ X, float* __restrict__ R,
                 ull* __restrict__ bestInit) {
    int n = blockIdx.x * 8 + (threadIdx.x >> 5);
    int l = threadIdx.x & 31;
    const float* xp = X + (size_t)n * 256 + l;
    float si[8];
    #pragma unroll
    for (int i = 0; i < 8; i++) {
        float v = xp[i * 32];
        si[i] = warp_red(__fmul_rn(v, v));
    }
    float s = combine8(si);
    if (l == 0) {
        R[n] = s;
        if (bestInit) bestInit[n] = ~0ull;
    }
}

__global__ __launch_bounds__(256, 2)
void k_vq(const float* __restrict__ A, const float* __restrict__ CB,
          const float* __restrict__ rr, const float* __restrict__ cn,
          ull* __restrict__ best) {
    __shared__ float As[2][BK][BM + APAD];
    __shared__ float Bs[2][BK][BN + BPAD];
    __shared__ ull sbest[BM];
    const int K = 256;
    int t = threadIdx.x;
    int tx4 = (t & 15) * 4, ty8 = (t >> 4) * 8;
    int rowBase = blockIdx.y * BM, colBase = blockIdx.x * BN;
    int ar = t >> 1, ak = (t & 1) * 8;
    int lc = t >> 1, kd = (t & 1) * 8;
    if (t < BM) sbest[t] = ~0ull;
    const float* Ap = A + (size_t)(rowBase + ar) * K + ak;
    const float* Cp = CB + (size_t)(colBase + lc) * K + kd;
    float2 acc[8][4];
    #pragma unroll
    for (int i = 0; i < 8; i++)
        #pragma unroll
        for (int j = 0; j < 4; j++) acc[i][j] = make_float2(0.f, 0.f);
    {
        float4 ra0 = *(const float4*)(Ap);
        float4 ra1 = *(const float4*)(Ap + 4);
        As[0][ak + 0][ar] = ra0.x; As[0][ak + 1][ar] = ra0.y;
        As[0][ak + 2][ar] = ra0.z; As[0][ak + 3][ar] = ra0.w;
        As[0][ak + 4][ar] = ra1.x; As[0][ak + 5][ar] = ra1.y;
        As[0][ak + 6][ar] = ra1.z; As[0][ak + 7][ar] = ra1.w;
        float4 rb0 = *(const float4*)(Cp);
        float4 rb1 = *(const float4*)(Cp + 4);
        Bs[0][kd + 0][lc] = rb0.x; Bs[0][kd + 1][lc] = rb0.y;
        Bs[0][kd + 2][lc] = rb0.z; Bs[0][kd + 3][lc] = rb0.w;
        Bs[0][kd + 4][lc] = rb1.x; Bs[0][kd + 5][lc] = rb1.y;
        Bs[0][kd + 6][lc] = rb1.z; Bs[0][kd + 7][lc] = rb1.w;
    }
    __syncthreads();
    const int nk = K / BK;
    #pragma unroll 1
    for (int kt = 0; kt < nk; kt++) {
        int cur = kt & 1;
        bool more = (kt + 1 < nk);
        float4 ra0, ra1, rb0, rb1;
        if (more) {
            ra0 = *(const float4*)(Ap + (kt + 1) * BK);
            ra1 = *(const float4*)(Ap + (kt + 1) * BK + 4);
            rb0 = *(const float4*)(Cp + (kt + 1) * BK);
            rb1 = *(const float4*)(Cp + (kt + 1) * BK + 4);
        }
        #pragma unroll
        for (int kk = 0; kk < BK; kk++) {
            float4 a0 = *(const float4*)&As[cur][kk][ty8];
            float4 a1 = *(const float4*)&As[cur][kk][ty8 + 4];
            float4 b0 = *(const float4*)&Bs[cur][kk][tx4];
            float4 b1 = *(const float4*)&Bs[cur][kk][tx4 + 64];
            MMA_STEP(acc, a0, a1, b0, b1)
        }
        if (more) {
            int nb = cur ^ 1;
            As[nb][ak + 0][ar] = ra0.x; As[nb][ak + 1][ar] = ra0.y;
            As[nb][ak + 2][ar] = ra0.z; As[nb][ak + 3][ar] = ra0.w;
            As[nb][ak + 4][ar] = ra1.x; As[nb][ak + 5][ar] = ra1.y;
            As[nb][ak + 6][ar] = ra1.z; As[nb][ak + 7][ar] = ra1.w;
            Bs[nb][kd + 0][lc] = rb0.x; Bs[nb][kd + 1][lc] = rb0.y;
            Bs[nb][kd + 2][lc] = rb0.z; Bs[nb][kd + 3][lc] = rb0.w;
            Bs[nb][kd + 4][lc] = rb1.x; Bs[nb][kd + 5][lc] = rb1.y;
            Bs[nb][kd + 6][lc] = rb1.z; Bs[nb][kd + 7][lc] = rb1.w;
        }
        __syncthreads();
    }
    float4 c0 = *(const float4*)(cn + colBase + tx4);
    float4 c1 = *(const float4*)(cn + colBase + tx4 + 64);
    float cc[8] = {c0.x, c0.y, c0.z, c0.w, c1.x, c1.y, c1.z, c1.w};
    int codes[8];
    #pragma unroll
    for (int j = 0; j < 4; j++) { codes[j] = colBase + tx4 + j; codes[4 + j] = colBase + tx4 + 64 + j; }
    #pragma unroll
    for (int i = 0; i < 8; i++) {
        float rrow = rr[rowBase + ty8 + i];
        float v[8] = {acc[i][0].x, acc[i][0].y, acc[i][1].x, acc[i][1].y,
                      acc[i][2].x, acc[i][2].y, acc[i][3].x, acc[i][3].y};
        ull mykey = ~0ull;
        #pragma unroll
        for (int j = 0; j < 8; j++) {
            float m2 = __fmul_rn(2.0f, v[j]);
            float t1 = __fsub_rn(rrow, m2);
            float d2 = __fadd_rn(t1, cc[j]);
            ull key = ((ull)__float_as_uint(d2) << 32) | (unsigned)codes[j];
            if (key < mykey) mykey = key;
        }
        atomicMin(&sbest[ty8 + i], mykey);
    }
    __syncthreads();
    if (t < BM) atomicMin(&best[rowBase + t], sbest[t]);
}

__global__ void k_vq_gather(const ull* __restrict__ best, const float* __restrict__ CB,
                            const float* __restrict__ enc, float* __restrict__ qn,
                            float* __restrict__ out_idx) {
    int n = blockIdx.x, c = threadIdx.x;
    int k = (int)(unsigned)(best[n] & 0xFFFFFFFFull);
    float q = CB[k * 256 + c];
    float inp = enc[n * 256 + c];
    qn[n * 256 + c] = __fsub_rn(__fadd_rn(q, inp), inp);
    if (c == 0) out_idx[n] = (float)k;
}

// ---------------- host side ---------------------------------------------------
static void run_block(const float* cur, float* nxt, const float* const* p, int off, int d,
                      float* LN, float* Cbuf, float* grn, float* nx, float* cwT) {
    const float* cw  = p[off + 0] + d * 256 * 49;
    const float* cbi = p[off + 1] + d * 256;
    const float* lng = p[off + 2] + d * 256;
    const float* lnb = p[off + 3] + d * 256;
    const float* w1  = p[off + 4] + d * 256 * 1024;
    const float* b1  = p[off + 5] + d * 1024;
    const float* gg  = p[off + 6] + d * 1024;
    const float* gb  = p[off + 7] + d * 1024;
    const float* w2  = p[off + 8] + d * 1024 * 256;
    const float* b2  = p[off + 9] + d * 256;
    k_wtrans<<<49, 256>>>(cw, cwT);
    k_conv_ln<<<NROW / 32, 256>>>(cur, LN, cwT, cbi, lng, lnb);
    k_fc1<<<dim3(INTER / BN, NROW / BM), 256>>>(LN, w1, b1, Cbuf);
    k_grn_sumsq<<<dim3(32, 8), dim3(32, 32)>>>(Cbuf, grn);
    k_grn_nx<<<BB, 1024>>>(grn, nx);
    k_fc2<<<dim3(CC / BN, NROW / BM), 256>>>(Cbuf, w2, nx, gg, gb, b2, cur, nxt);
}

extern "C" void kernel_launch(void* const* d_in, const int* in_sizes, int n_in,
                              void* d_out, int out_size) {
    const float* x  = (const float*)d_in[0];
    const float* cb = (const float*)d_in[1];
    const float* p[20];
    for (int i = 0; i < 20; i++) p[i] = (const float*)d_in[2 + i];
    float* out = (float*)d_out;

    float *A0, *A1, *LN, *Cbuf, *grn, *nx, *rr, *cn, *cwT;
    ull* best;
    cudaGetSymbolAddress((void**)&A0,   g_A0);
    cudaGetSymbolAddress((void**)&A1,   g_A1);
    cudaGetSymbolAddress((void**)&LN,   g_LN);
    cudaGetSymbolAddress((void**)&Cbuf, g_C);
    cudaGetSymbolAddress((void**)&grn,  g_grn);
    cudaGetSymbolAddress((void**)&nx,   g_scl);
    cudaGetSymbolAddress((void**)&rr,   g_r);
    cudaGetSymbolAddress((void**)&cn,   g_cn);
    cudaGetSymbolAddress((void**)&best, g_best);
    cudaGetSymbolAddress((void**)&cwT,  g_cwT);

    dim3 tt(32, 8);
    k_rownorm_w<<<KCB / 8, 256>>>(cb, cn, (ull*)0);
    k_transpose<<<dim3(128, 8, 8), tt>>>(x, A0, 256, 4096);

    float* cur = A0;
    float* nxt = A1;
    for (int d = 0; d < 2; d++) {
        run_block(cur, nxt, p, 0, d, LN, Cbuf, grn, nx, cwT);
        float* tmp = cur; cur = nxt; nxt = tmp;
    }
    k_rownorm_w<<<NROW / 8, 256>>>(cur, rr, best);
    k_vq<<<dim3(KCB / BN, NROW / BM), 256>>>(cur, cb, rr, cn, best);
    k_vq_gather<<<NROW, 256>>>(best, cb, cur, nxt, out + 2 * NROW * CC);
    k_transpose<<<dim3(8, 128, 8), tt>>>(nxt, out, 4096, 256);
    cur = nxt;
    nxt = (cur == A0) ? A1 : A0;
    for (int d = 0; d < 2; d++) {
        run_block(cur, nxt, p, 10, d, LN, Cbuf, grn, nx, cwT);
        float* tmp = cur; cur = nxt; nxt = tmp;
    }
    k_transpose<<<dim3(8, 128, 8), tt>>>(cur, out + NROW * CC, 4096, 256);
}